// round 2
// baseline (speedup 1.0000x reference)
#include <cuda_runtime.h>
#include <cuda_bf16.h>
#include <cstdint>

// Problem constants
#define B_  2
#define S_  2048
#define E_  1024
#define NH_ 16
#define NKV_ 4
#define HD_ 64
#define GS_ 4           // NH/NKV
#define MTOT (B_*S_)    // 4096

// Scratch (no cudaMalloc allowed)
__device__ float g_q[MTOT * (NH_*HD_)];     // [B*S, 1024]
__device__ float g_k[MTOT * (NKV_*HD_)];    // [B*S, 256]
__device__ float g_v[MTOT * (NKV_*HD_)];    // [B*S, 256]
__device__ float g_attn[MTOT * (NH_*HD_)];  // [B*S, 1024]

// ---------------------------------------------------------------------------
// GEMM: C[M,N] = X[M,K] @ W[N,K]^T   (row-major X, row-major W)
// Tile 64x64, K-tile 16, 256 threads, 4x4 per thread.
// All dims are multiples of the tiles (M=4096, N in {256,1024}, K=1024).
// ---------------------------------------------------------------------------
__global__ __launch_bounds__(256)
void gemm_xwt_kernel(const float* __restrict__ X, const float* __restrict__ W,
                     float* __restrict__ C, int M, int N, int K)
{
    __shared__ float Xs[64][17];   // [row][kk] padded
    __shared__ float Ws[64][17];   // [col][kk] padded

    const int tx = threadIdx.x & 15;   // 0..15
    const int ty = threadIdx.x >> 4;   // 0..15
    const int m0 = blockIdx.y * 64;
    const int n0 = blockIdx.x * 64;

    float c[4][4];
    #pragma unroll
    for (int i = 0; i < 4; i++)
        #pragma unroll
        for (int j = 0; j < 4; j++) c[i][j] = 0.f;

    const int nKT = K / 16;
    for (int kt = 0; kt < nKT; kt++) {
        const int k0 = kt * 16;
        // load 64x16 X tile and 64x16 W tile; 1024 elems each, 256 thr -> 4 each
        #pragma unroll
        for (int l = 0; l < 4; l++) {
            int idx = threadIdx.x + l * 256;      // 0..1023
            int r = idx >> 4;                     // 0..63
            int kk = idx & 15;                    // 0..15
            Xs[r][kk] = X[(size_t)(m0 + r) * K + k0 + kk];
            Ws[r][kk] = W[(size_t)(n0 + r) * K + k0 + kk];
        }
        __syncthreads();

        #pragma unroll
        for (int kk = 0; kk < 16; kk++) {
            float a[4], b[4];
            #pragma unroll
            for (int i = 0; i < 4; i++) a[i] = Xs[ty * 4 + i][kk];
            #pragma unroll
            for (int j = 0; j < 4; j++) b[j] = Ws[tx * 4 + j][kk];
            #pragma unroll
            for (int i = 0; i < 4; i++)
                #pragma unroll
                for (int j = 0; j < 4; j++)
                    c[i][j] += a[i] * b[j];
        }
        __syncthreads();
    }

    #pragma unroll
    for (int i = 0; i < 4; i++) {
        const size_t row = (size_t)(m0 + ty * 4 + i) * N + n0;
        #pragma unroll
        for (int j = 0; j < 4; j++)
            C[row + tx * 4 + j] = c[i][j];
    }
}

// ---------------------------------------------------------------------------
// Causal flash attention, GQA.
// grid: (S/128, NH, B). block: 128 threads; thread t owns q-row qb*128+t.
// Q: [B,S,NH*HD] (g_q), K/V: [B,S,NKV*HD], out: [B,S,NH*HD]
// ---------------------------------------------------------------------------
#define BQ 128
#define BK 32

__global__ __launch_bounds__(BQ)
void attn_kernel(const float* __restrict__ Q, const float* __restrict__ K,
                 const float* __restrict__ V, float* __restrict__ O)
{
    const int qb  = blockIdx.x;
    const int h   = blockIdx.y;
    const int b   = blockIdx.z;
    const int tid = threadIdx.x;
    const int qi  = qb * BQ + tid;          // global q index (< S always)
    const int kvh = h / GS_;

    __shared__ float Ks[BK][HD_];           // broadcast reads -> no conflicts
    __shared__ float Vs[BK][HD_];
    __shared__ float Ss[BQ][BK + 1];        // padded score strip

    const float scale = 0.125f;             // 1/sqrt(64)

    float qreg[HD_];
    {
        const float* qp = Q + ((size_t)b * S_ + qi) * (NH_ * HD_) + h * HD_;
        #pragma unroll
        for (int d = 0; d < HD_; d++) qreg[d] = qp[d] * scale;
    }

    float acc[HD_];
    #pragma unroll
    for (int d = 0; d < HD_; d++) acc[d] = 0.f;
    float m = -1e30f, l = 0.f;

    const int kmax = qb * BQ + (BQ - 1);    // furthest k any row in this block needs
    const int nKT  = (kmax / BK) + 1;

    for (int kt = 0; kt < nKT; kt++) {
        const int base = kt * BK;
        // load K/V tile: BK*HD = 2048 elems, 128 thr -> 16 each, coalesced in d
        for (int i = tid; i < BK * HD_; i += BQ) {
            const int r = i >> 6;           // /HD
            const int d = i & 63;
            const size_t gofs = ((size_t)b * S_ + base + r) * (NKV_ * HD_) + kvh * HD_ + d;
            Ks[r][d] = K[gofs];
            Vs[r][d] = V[gofs];
        }
        __syncthreads();

        // scores for my row
        float mt = m;
        for (int j = 0; j < BK; j++) {
            float sj = 0.f;
            #pragma unroll
            for (int d = 0; d < HD_; d++) sj += qreg[d] * Ks[j][d];
            sj = (base + j <= qi) ? sj : -1e30f;
            Ss[tid][j] = sj;
            mt = fmaxf(mt, sj);
        }

        const float corr = __expf(m - mt);
        l *= corr;
        #pragma unroll
        for (int d = 0; d < HD_; d++) acc[d] *= corr;

        for (int j = 0; j < BK; j++) {
            const float p = __expf(Ss[tid][j] - mt);
            l += p;
            #pragma unroll
            for (int d = 0; d < HD_; d++) acc[d] += p * Vs[j][d];
        }
        m = mt;
        __syncthreads();
    }

    const float inv = 1.f / l;
    float* op = O + ((size_t)b * S_ + qi) * (NH_ * HD_) + h * HD_;
    #pragma unroll
    for (int d = 0; d < HD_; d++) op[d] = acc[d] * inv;
}

// ---------------------------------------------------------------------------
// Launch
// Inputs (metadata order): 0 query, 1 key, 2 value, 3 attn_mask,
//                          4 Wq, 5 Wk, 6 Wv, 7 Wo
// ---------------------------------------------------------------------------
extern "C" void kernel_launch(void* const* d_in, const int* in_sizes, int n_in,
                              void* d_out, int out_size)
{
    const float* query = (const float*)d_in[0];
    const float* key   = (const float*)d_in[1];
    const float* value = (const float*)d_in[2];
    const float* Wq    = (const float*)d_in[4];
    const float* Wk    = (const float*)d_in[5];
    const float* Wv    = (const float*)d_in[6];
    const float* Wo    = (const float*)d_in[7];
    float* out = (float*)d_out;

    float *q, *k, *v, *attn;
    cudaGetSymbolAddress((void**)&q,    g_q);
    cudaGetSymbolAddress((void**)&k,    g_k);
    cudaGetSymbolAddress((void**)&v,    g_v);
    cudaGetSymbolAddress((void**)&attn, g_attn);

    dim3 thr(256);
    // Q projection: [4096,1024] = query @ Wq^T
    gemm_xwt_kernel<<<dim3((NH_*HD_)/64, MTOT/64), thr>>>(query, Wq, q, MTOT, NH_*HD_, E_);
    // K/V projections: [4096,256]
    gemm_xwt_kernel<<<dim3((NKV_*HD_)/64, MTOT/64), thr>>>(key,   Wk, k, MTOT, NKV_*HD_, E_);
    gemm_xwt_kernel<<<dim3((NKV_*HD_)/64, MTOT/64), thr>>>(value, Wv, v, MTOT, NKV_*HD_, E_);

    // attention
    attn_kernel<<<dim3(S_/BQ, NH_, B_), dim3(BQ)>>>(q, k, v, attn);

    // O projection: out = attn @ Wo^T  [4096,1024]
    gemm_xwt_kernel<<<dim3(E_/64, MTOT/64), thr>>>(attn, Wo, out, MTOT, E_, E_);
}

// round 4
// speedup vs baseline: 1.3583x; 1.3583x over previous
#include <cuda_runtime.h>
#include <cuda_bf16.h>
#include <mma.h>
#include <cstdint>

using namespace nvcuda;

// Problem constants
#define B_  2
#define S_  2048
#define E_  1024
#define NH_ 16
#define NKV_ 4
#define HD_ 64
#define GS_ 4           // NH/NKV
#define MTOT (B_*S_)    // 4096

// Scratch (no cudaMalloc allowed)
__device__ float g_q[MTOT * (NH_*HD_)];     // [B*S, 1024]
__device__ float g_k[MTOT * (NKV_*HD_)];    // [B*S, 256]
__device__ float g_v[MTOT * (NKV_*HD_)];    // [B*S, 256]
__device__ float g_attn[MTOT * (NH_*HD_)];  // [B*S, 1024]

// ---------------------------------------------------------------------------
// tf32 tensor-core GEMM: C[M,N] = X[M,K] @ W[N,K]^T
// Block tile 128x128, K-tile 32. 256 threads = 8 warps, warp tile 64x32
// (4x2 wmma 16x16x8 tf32 fragments).
// ---------------------------------------------------------------------------
#define BM 128
#define BN 128
#define BKG 32
#define LDS_PAD (BKG + 4)   // 36 floats = 144B, multiple of 16B

__global__ __launch_bounds__(256)
void gemm_tf32_kernel(const float* __restrict__ X, const float* __restrict__ W,
                      float* __restrict__ C, int M, int N, int K)
{
    __shared__ float Xs[BM][LDS_PAD];
    __shared__ float Ws[BN][LDS_PAD];

    const int tid = threadIdx.x;
    const int wid = tid >> 5;
    const int wr  = wid & 1;      // 0..1 -> 64-row group
    const int wc  = wid >> 1;     // 0..3 -> 32-col group
    const int m0  = blockIdx.y * BM;
    const int n0  = blockIdx.x * BN;

    wmma::fragment<wmma::accumulator, 16, 16, 8, float> acc[4][2];
    #pragma unroll
    for (int i = 0; i < 4; i++)
        #pragma unroll
        for (int j = 0; j < 2; j++)
            wmma::fill_fragment(acc[i][j], 0.0f);

    for (int k0 = 0; k0 < K; k0 += BKG) {
        // Stage 128x32 of X and of W into shared (tf32-converted).
        #pragma unroll
        for (int l = 0; l < 4; l++) {
            int idx = tid + l * 256;      // 0..1023 float4 slots
            int r   = idx >> 3;           // 0..127
            int c4  = idx & 7;            // 0..7
            float4 xv = *(const float4*)&X[(size_t)(m0 + r) * K + k0 + c4 * 4];
            float4 wv = *(const float4*)&W[(size_t)(n0 + r) * K + k0 + c4 * 4];
            xv.x = wmma::__float_to_tf32(xv.x); xv.y = wmma::__float_to_tf32(xv.y);
            xv.z = wmma::__float_to_tf32(xv.z); xv.w = wmma::__float_to_tf32(xv.w);
            wv.x = wmma::__float_to_tf32(wv.x); wv.y = wmma::__float_to_tf32(wv.y);
            wv.z = wmma::__float_to_tf32(wv.z); wv.w = wmma::__float_to_tf32(wv.w);
            *(float4*)&Xs[r][c4 * 4] = xv;
            *(float4*)&Ws[r][c4 * 4] = wv;
        }
        __syncthreads();

        #pragma unroll
        for (int ks = 0; ks < BKG; ks += 8) {
            wmma::fragment<wmma::matrix_a, 16, 16, 8, wmma::precision::tf32, wmma::row_major> a[4];
            wmma::fragment<wmma::matrix_b, 16, 16, 8, wmma::precision::tf32, wmma::col_major> bfr[2];
            #pragma unroll
            for (int i = 0; i < 4; i++)
                wmma::load_matrix_sync(a[i], &Xs[wr * 64 + i * 16][ks], LDS_PAD);
            #pragma unroll
            for (int j = 0; j < 2; j++)
                wmma::load_matrix_sync(bfr[j], &Ws[wc * 32 + j * 16][ks], LDS_PAD);
            #pragma unroll
            for (int i = 0; i < 4; i++)
                #pragma unroll
                for (int j = 0; j < 2; j++)
                    wmma::mma_sync(acc[i][j], a[i], bfr[j], acc[i][j]);
        }
        __syncthreads();
    }

    #pragma unroll
    for (int i = 0; i < 4; i++)
        #pragma unroll
        for (int j = 0; j < 2; j++)
            wmma::store_matrix_sync(&C[(size_t)(m0 + wr * 64 + i * 16) * N + n0 + wc * 32 + j * 16],
                                    acc[i][j], N, wmma::mem_row_major);
}

// ---------------------------------------------------------------------------
// Causal flash attention, GQA. Lane-pair split over head dim:
// thread t -> q-row (t>>1), half (t&1). Each half owns 8 interleaved float4
// chunks: chunk index c = 2*i + half, dims 4c..4c+3. QK dot combined via
// shfl_xor(.,1). Online softmax. BK=32 tiles, block = 128 rows / 256 threads.
// ---------------------------------------------------------------------------
#define BQ 128
#define BK 32

__global__ __launch_bounds__(256)
void attn_kernel(const float* __restrict__ Q, const float* __restrict__ K,
                 const float* __restrict__ V, float* __restrict__ O)
{
    const int qb   = gridDim.x - 1 - blockIdx.x;   // long blocks first
    const int h    = blockIdx.y;
    const int b    = blockIdx.z;
    const int tid  = threadIdx.x;
    const int row  = tid >> 1;
    const int half = tid & 1;
    const int qi   = qb * BQ + row;
    const int kvh  = h / GS_;

    __shared__ float Ks[BK][HD_];
    __shared__ float Vs[BK][HD_];
    __shared__ float Ss[BQ][BK + 1];

    const float scale = 0.125f;   // 1/sqrt(64)

    float4 qv[8], av[8];
    {
        const float* qp = Q + ((size_t)(b * S_ + qi)) * (NH_ * HD_) + h * HD_;
        #pragma unroll
        for (int i = 0; i < 8; i++) {
            float4 t = *(const float4*)(qp + (2 * i + half) * 4);
            qv[i] = make_float4(t.x * scale, t.y * scale, t.z * scale, t.w * scale);
            av[i] = make_float4(0.f, 0.f, 0.f, 0.f);
        }
    }
    float m = -1e30f, l = 0.f;

    const int nKT = (qb * BQ + BQ - 1) / BK + 1;

    for (int kt = 0; kt < nKT; kt++) {
        const int base = kt * BK;
        __syncthreads();
        // load K/V tile: BK*HD/4 = 512 float4 each; 256 threads -> 2 each
        #pragma unroll
        for (int idx = tid; idx < BK * HD_ / 4; idx += 256) {
            int r = idx >> 4;        // /(HD/4)
            int c = idx & 15;
            size_t g = ((size_t)(b * S_ + base + r)) * (NKV_ * HD_) + kvh * HD_ + c * 4;
            *(float4*)&Ks[r][c * 4] = *(const float4*)&K[g];
            *(float4*)&Vs[r][c * 4] = *(const float4*)&V[g];
        }
        __syncthreads();

        // phase 1: scores + running max
        float mt = m;
        #pragma unroll 4
        for (int j = 0; j < BK; j++) {
            float p0 = 0.f;
            #pragma unroll
            for (int i = 0; i < 8; i++) {
                const float4 kv4 = *(const float4*)&Ks[j][(2 * i + half) * 4];
                p0 += qv[i].x * kv4.x + qv[i].y * kv4.y + qv[i].z * kv4.z + qv[i].w * kv4.w;
            }
            float s = p0 + __shfl_xor_sync(0xffffffffu, p0, 1);
            s = (base + j <= qi) ? s : -1e30f;
            if (!half) Ss[row][j] = s;
            mt = fmaxf(mt, s);
        }
        __syncwarp();

        // rescale
        const float corr = __expf(m - mt);
        l *= corr;
        #pragma unroll
        for (int i = 0; i < 8; i++) {
            av[i].x *= corr; av[i].y *= corr; av[i].z *= corr; av[i].w *= corr;
        }

        // phase 2: probs + PV
        #pragma unroll 4
        for (int j = 0; j < BK; j++) {
            const float p = __expf(Ss[row][j] - mt);
            l += p;
            #pragma unroll
            for (int i = 0; i < 8; i++) {
                const float4 vv = *(const float4*)&Vs[j][(2 * i + half) * 4];
                av[i].x += p * vv.x; av[i].y += p * vv.y;
                av[i].z += p * vv.z; av[i].w += p * vv.w;
            }
        }
        m = mt;
    }

    const float inv = 1.f / l;
    float* op = O + ((size_t)(b * S_ + qi)) * (NH_ * HD_) + h * HD_;
    #pragma unroll
    for (int i = 0; i < 8; i++) {
        float4 o4 = make_float4(av[i].x * inv, av[i].y * inv, av[i].z * inv, av[i].w * inv);
        *(float4*)(op + (2 * i + half) * 4) = o4;
    }
}

// ---------------------------------------------------------------------------
// Launch. Inputs: 0 query, 1 key, 2 value, 3 attn_mask, 4 Wq, 5 Wk, 6 Wv, 7 Wo
// ---------------------------------------------------------------------------
extern "C" void kernel_launch(void* const* d_in, const int* in_sizes, int n_in,
                              void* d_out, int out_size)
{
    const float* query = (const float*)d_in[0];
    const float* key   = (const float*)d_in[1];
    const float* value = (const float*)d_in[2];
    const float* Wq    = (const float*)d_in[4];
    const float* Wk    = (const float*)d_in[5];
    const float* Wv    = (const float*)d_in[6];
    const float* Wo    = (const float*)d_in[7];
    float* out = (float*)d_out;

    float *q, *k, *v, *attn;
    cudaGetSymbolAddress((void**)&q,    g_q);
    cudaGetSymbolAddress((void**)&k,    g_k);
    cudaGetSymbolAddress((void**)&v,    g_v);
    cudaGetSymbolAddress((void**)&attn, g_attn);

    dim3 thr(256);
    // Q projection: [4096,1024]
    gemm_tf32_kernel<<<dim3((NH_*HD_)/BN, MTOT/BM), thr>>>(query, Wq, q, MTOT, NH_*HD_, E_);
    // K/V projections: [4096,256]
    gemm_tf32_kernel<<<dim3((NKV_*HD_)/BN, MTOT/BM), thr>>>(key,   Wk, k, MTOT, NKV_*HD_, E_);
    gemm_tf32_kernel<<<dim3((NKV_*HD_)/BN, MTOT/BM), thr>>>(value, Wv, v, MTOT, NKV_*HD_, E_);

    // attention
    attn_kernel<<<dim3(S_/BQ, NH_, B_), dim3(256)>>>(q, k, v, attn);

    // O projection: out = attn @ Wo^T  [4096,1024]
    gemm_tf32_kernel<<<dim3(E_/BN, MTOT/BM), thr>>>(attn, Wo, out, MTOT, E_, E_);
}

// round 5
// speedup vs baseline: 2.0434x; 1.5044x over previous
#include <cuda_runtime.h>
#include <cuda_bf16.h>
#include <mma.h>
#include <cstdint>

using namespace nvcuda;

// Problem constants
#define B_  2
#define S_  2048
#define E_  1024
#define NH_ 16
#define NKV_ 4
#define HD_ 64
#define GS_ 4
#define MTOT (B_*S_)    // 4096

// Scratch
__device__ float g_q[MTOT * (NH_*HD_)];
__device__ float g_k[MTOT * (NKV_*HD_)];
__device__ float g_v[MTOT * (NKV_*HD_)];
__device__ float g_attn[MTOT * (NH_*HD_)];

// ---------------------------------------------------------------------------
// tf32 tensor-core GEMM (unchanged from R3): C[M,N] = X[M,K] @ W[N,K]^T
// ---------------------------------------------------------------------------
#define BM 128
#define BN 128
#define BKG 32
#define LDS_PAD (BKG + 4)

__global__ __launch_bounds__(256)
void gemm_tf32_kernel(const float* __restrict__ X, const float* __restrict__ W,
                      float* __restrict__ C, int M, int N, int K)
{
    __shared__ float Xs[BM][LDS_PAD];
    __shared__ float Ws[BN][LDS_PAD];

    const int tid = threadIdx.x;
    const int wid = tid >> 5;
    const int wr  = wid & 1;
    const int wc  = wid >> 1;
    const int m0  = blockIdx.y * BM;
    const int n0  = blockIdx.x * BN;

    wmma::fragment<wmma::accumulator, 16, 16, 8, float> acc[4][2];
    #pragma unroll
    for (int i = 0; i < 4; i++)
        #pragma unroll
        for (int j = 0; j < 2; j++)
            wmma::fill_fragment(acc[i][j], 0.0f);

    for (int k0 = 0; k0 < K; k0 += BKG) {
        #pragma unroll
        for (int l = 0; l < 4; l++) {
            int idx = tid + l * 256;
            int r   = idx >> 3;
            int c4  = idx & 7;
            float4 xv = *(const float4*)&X[(size_t)(m0 + r) * K + k0 + c4 * 4];
            float4 wv = *(const float4*)&W[(size_t)(n0 + r) * K + k0 + c4 * 4];
            xv.x = wmma::__float_to_tf32(xv.x); xv.y = wmma::__float_to_tf32(xv.y);
            xv.z = wmma::__float_to_tf32(xv.z); xv.w = wmma::__float_to_tf32(xv.w);
            wv.x = wmma::__float_to_tf32(wv.x); wv.y = wmma::__float_to_tf32(wv.y);
            wv.z = wmma::__float_to_tf32(wv.z); wv.w = wmma::__float_to_tf32(wv.w);
            *(float4*)&Xs[r][c4 * 4] = xv;
            *(float4*)&Ws[r][c4 * 4] = wv;
        }
        __syncthreads();

        #pragma unroll
        for (int ks = 0; ks < BKG; ks += 8) {
            wmma::fragment<wmma::matrix_a, 16, 16, 8, wmma::precision::tf32, wmma::row_major> a[4];
            wmma::fragment<wmma::matrix_b, 16, 16, 8, wmma::precision::tf32, wmma::col_major> bfr[2];
            #pragma unroll
            for (int i = 0; i < 4; i++)
                wmma::load_matrix_sync(a[i], &Xs[wr * 64 + i * 16][ks], LDS_PAD);
            #pragma unroll
            for (int j = 0; j < 2; j++)
                wmma::load_matrix_sync(bfr[j], &Ws[wc * 32 + j * 16][ks], LDS_PAD);
            #pragma unroll
            for (int i = 0; i < 4; i++)
                #pragma unroll
                for (int j = 0; j < 2; j++)
                    wmma::mma_sync(acc[i][j], a[i], bfr[j], acc[i][j]);
        }
        __syncthreads();
    }

    #pragma unroll
    for (int i = 0; i < 4; i++)
        #pragma unroll
        for (int j = 0; j < 2; j++)
            wmma::store_matrix_sync(&C[(size_t)(m0 + wr * 64 + i * 16) * N + n0 + wc * 32 + j * 16],
                                    acc[i][j], N, wmma::mem_row_major);
}

// ---------------------------------------------------------------------------
// Tensor-core flash attention (3xTF32, mma.m16n8k8).
// CTA: 128 threads (4 warps). BQ=64 (16 rows/warp), BK=32, HD=64.
// Q A-frags (hi+lo) register-resident; K/V pre-split hi/lo into shared.
// Softmax fp32 in C-fragment layout; P re-laid out via per-warp shared buffer.
// ---------------------------------------------------------------------------
#define ABQ 64
#define ABK 32

__device__ __forceinline__ uint32_t f2tf(float x) {
    uint32_t u;
    asm("cvt.rna.tf32.f32 %0, %1;" : "=r"(u) : "f"(x));
    return u;
}

__device__ __forceinline__ void mma_tf32(float c[4], const uint32_t a[4],
                                         uint32_t b0, uint32_t b1)
{
    asm volatile(
        "mma.sync.aligned.m16n8k8.row.col.f32.tf32.tf32.f32 "
        "{%0,%1,%2,%3}, {%4,%5,%6,%7}, {%8,%9}, {%0,%1,%2,%3};"
        : "+f"(c[0]), "+f"(c[1]), "+f"(c[2]), "+f"(c[3])
        : "r"(a[0]), "r"(a[1]), "r"(a[2]), "r"(a[3]), "r"(b0), "r"(b1));
}

__global__ __launch_bounds__(128, 3)
void attn_mma_kernel(const float* __restrict__ Q, const float* __restrict__ K,
                     const float* __restrict__ V, float* __restrict__ O)
{
    // sbuf: [sKhi | sKlo | sVhi | sVlo], each [32][68] u32. Q staged (as float)
    // aliases the first half before the main loop.
    __shared__ uint32_t sbuf[4 * 32 * 68];
    __shared__ float    sP[4][16 * 36];   // per-warp P buffer [16][36]

    uint32_t* sKhi = sbuf;
    uint32_t* sKlo = sbuf + 2176;
    uint32_t* sVhi = sbuf + 4352;
    uint32_t* sVlo = sbuf + 6528;
    float*    sQ   = (float*)sbuf;        // [64][68]

    const int qb   = gridDim.x - 1 - blockIdx.x;   // long causal blocks first
    const int h    = blockIdx.y;
    const int b    = blockIdx.z;
    const int kvh  = h >> 2;                        // h / GS
    const int tid  = threadIdx.x;
    const int lane = tid & 31;
    const int w    = tid >> 5;
    const int g    = lane >> 2;
    const int tig  = lane & 3;

    const float scale = 0.125f;

    // ---- stage Q tile [64][64] (scaled) ----
    for (int i = tid; i < 64 * 16; i += 128) {
        int r = i >> 4, c4 = i & 15;
        float4 qv = *(const float4*)&Q[((size_t)(b * S_ + qb * ABQ + r)) * (NH_*HD_) + h * HD_ + c4 * 4];
        qv.x *= scale; qv.y *= scale; qv.z *= scale; qv.w *= scale;
        *(float4*)&sQ[r * 68 + c4 * 4] = qv;
    }
    __syncthreads();

    // ---- Q A-fragments (hi/lo), rows w*16+g, w*16+g+8 ----
    uint32_t qhi[8][4], qlo[8][4];
    {
        const int ra = w * 16 + g;
        #pragma unroll
        for (int kb = 0; kb < 8; kb++) {
            float a0 = sQ[ra * 68 + kb * 8 + tig];
            float a1 = sQ[(ra + 8) * 68 + kb * 8 + tig];
            float a2 = sQ[ra * 68 + kb * 8 + tig + 4];
            float a3 = sQ[(ra + 8) * 68 + kb * 8 + tig + 4];
            qhi[kb][0] = f2tf(a0); qlo[kb][0] = f2tf(a0 - __uint_as_float(qhi[kb][0]));
            qhi[kb][1] = f2tf(a1); qlo[kb][1] = f2tf(a1 - __uint_as_float(qhi[kb][1]));
            qhi[kb][2] = f2tf(a2); qlo[kb][2] = f2tf(a2 - __uint_as_float(qhi[kb][2]));
            qhi[kb][3] = f2tf(a3); qlo[kb][3] = f2tf(a3 - __uint_as_float(qhi[kb][3]));
        }
    }
    __syncthreads();

    float oacc[8][4];
    #pragma unroll
    for (int nb = 0; nb < 8; nb++)
        #pragma unroll
        for (int e = 0; e < 4; e++) oacc[nb][e] = 0.f;
    float m0 = -1e30f, m1 = -1e30f, l0 = 0.f, l1 = 0.f;

    const int r0g = qb * ABQ + w * 16 + g;
    const int r1g = r0g + 8;
    const int wRowMax = qb * ABQ + w * 16 + 15;
    const int nKT = 2 * qb + 2;   // ceil((qb*64+64)/32)

    for (int kt = 0; kt < nKT; kt++) {
        // ---- load K/V tile, split hi/lo into shared ----
        for (int i = tid; i < ABK * 16; i += 128) {
            int r = i >> 4, c4 = i & 15;
            size_t gofs = ((size_t)(b * S_ + kt * ABK + r)) * (NKV_*HD_) + kvh * HD_ + c4 * 4;
            float4 kv = *(const float4*)&K[gofs];
            float4 vv = *(const float4*)&V[gofs];
            uint4 khi, klo, vhi, vlo;
            khi.x = f2tf(kv.x); klo.x = f2tf(kv.x - __uint_as_float(khi.x));
            khi.y = f2tf(kv.y); klo.y = f2tf(kv.y - __uint_as_float(khi.y));
            khi.z = f2tf(kv.z); klo.z = f2tf(kv.z - __uint_as_float(khi.z));
            khi.w = f2tf(kv.w); klo.w = f2tf(kv.w - __uint_as_float(khi.w));
            vhi.x = f2tf(vv.x); vlo.x = f2tf(vv.x - __uint_as_float(vhi.x));
            vhi.y = f2tf(vv.y); vlo.y = f2tf(vv.y - __uint_as_float(vhi.y));
            vhi.z = f2tf(vv.z); vlo.z = f2tf(vv.z - __uint_as_float(vhi.z));
            vhi.w = f2tf(vv.w); vlo.w = f2tf(vv.w - __uint_as_float(vhi.w));
            int o = r * 68 + c4 * 4;
            *(uint4*)&sKhi[o] = khi; *(uint4*)&sKlo[o] = klo;
            *(uint4*)&sVhi[o] = vhi; *(uint4*)&sVlo[o] = vlo;
        }
        __syncthreads();

        if (kt * ABK <= wRowMax) {
            // ---- S = Q @ K^T (3xTF32), per-warp 16x32 ----
            float sacc[4][4];
            #pragma unroll
            for (int nb = 0; nb < 4; nb++)
                #pragma unroll
                for (int e = 0; e < 4; e++) sacc[nb][e] = 0.f;

            #pragma unroll
            for (int kb = 0; kb < 8; kb++) {
                #pragma unroll
                for (int nb = 0; nb < 4; nb++) {
                    int jo = (nb * 8 + g) * 68 + kb * 8 + tig;
                    uint32_t bh0 = sKhi[jo], bh1 = sKhi[jo + 4];
                    uint32_t bl0 = sKlo[jo], bl1 = sKlo[jo + 4];
                    mma_tf32(sacc[nb], qhi[kb], bl0, bl1);
                    mma_tf32(sacc[nb], qlo[kb], bh0, bh1);
                    mma_tf32(sacc[nb], qhi[kb], bh0, bh1);
                }
            }

            // ---- causal mask + online softmax ----
            float mn0 = m0, mn1 = m1;
            #pragma unroll
            for (int nb = 0; nb < 4; nb++) {
                #pragma unroll
                for (int e = 0; e < 2; e++) {
                    int col = kt * ABK + nb * 8 + 2 * tig + e;
                    if (col > r0g) sacc[nb][e]     = -1e30f;
                    if (col > r1g) sacc[nb][e + 2] = -1e30f;
                    mn0 = fmaxf(mn0, sacc[nb][e]);
                    mn1 = fmaxf(mn1, sacc[nb][e + 2]);
                }
            }
            mn0 = fmaxf(mn0, __shfl_xor_sync(0xffffffffu, mn0, 1));
            mn0 = fmaxf(mn0, __shfl_xor_sync(0xffffffffu, mn0, 2));
            mn1 = fmaxf(mn1, __shfl_xor_sync(0xffffffffu, mn1, 1));
            mn1 = fmaxf(mn1, __shfl_xor_sync(0xffffffffu, mn1, 2));

            const float corr0 = __expf(m0 - mn0);
            const float corr1 = __expf(m1 - mn1);
            m0 = mn0; m1 = mn1;
            l0 *= corr0; l1 *= corr1;
            #pragma unroll
            for (int nb = 0; nb < 8; nb++) {
                oacc[nb][0] *= corr0; oacc[nb][1] *= corr0;
                oacc[nb][2] *= corr1; oacc[nb][3] *= corr1;
            }

            #pragma unroll
            for (int nb = 0; nb < 4; nb++) {
                float p0 = __expf(sacc[nb][0] - mn0);
                float p1 = __expf(sacc[nb][1] - mn0);
                float p2 = __expf(sacc[nb][2] - mn1);
                float p3 = __expf(sacc[nb][3] - mn1);
                l0 += p0 + p1; l1 += p2 + p3;
                int c = nb * 8 + 2 * tig;
                sP[w][g * 36 + c]       = p0;
                sP[w][g * 36 + c + 1]   = p1;
                sP[w][(g + 8) * 36 + c]     = p2;
                sP[w][(g + 8) * 36 + c + 1] = p3;
            }
            __syncwarp();

            // ---- O += P @ V (3xTF32) ----
            #pragma unroll
            for (int kb = 0; kb < 4; kb++) {
                float pa0 = sP[w][g * 36 + kb * 8 + tig];
                float pa1 = sP[w][(g + 8) * 36 + kb * 8 + tig];
                float pa2 = sP[w][g * 36 + kb * 8 + tig + 4];
                float pa3 = sP[w][(g + 8) * 36 + kb * 8 + tig + 4];
                uint32_t phi[4], plo[4];
                phi[0] = f2tf(pa0); plo[0] = f2tf(pa0 - __uint_as_float(phi[0]));
                phi[1] = f2tf(pa1); plo[1] = f2tf(pa1 - __uint_as_float(phi[1]));
                phi[2] = f2tf(pa2); plo[2] = f2tf(pa2 - __uint_as_float(phi[2]));
                phi[3] = f2tf(pa3); plo[3] = f2tf(pa3 - __uint_as_float(phi[3]));
                #pragma unroll
                for (int nb = 0; nb < 8; nb++) {
                    int jr = kb * 8 + tig;
                    int dc = nb * 8 + g;
                    uint32_t bh0 = sVhi[jr * 68 + dc], bh1 = sVhi[(jr + 4) * 68 + dc];
                    uint32_t bl0 = sVlo[jr * 68 + dc], bl1 = sVlo[(jr + 4) * 68 + dc];
                    mma_tf32(oacc[nb], phi, bl0, bl1);
                    mma_tf32(oacc[nb], plo, bh0, bh1);
                    mma_tf32(oacc[nb], phi, bh0, bh1);
                }
            }
        }
        __syncthreads();
    }

    // ---- epilogue: normalize + store ----
    l0 += __shfl_xor_sync(0xffffffffu, l0, 1);
    l0 += __shfl_xor_sync(0xffffffffu, l0, 2);
    l1 += __shfl_xor_sync(0xffffffffu, l1, 1);
    l1 += __shfl_xor_sync(0xffffffffu, l1, 2);
    const float inv0 = 1.f / l0;
    const float inv1 = 1.f / l1;

    #pragma unroll
    for (int nb = 0; nb < 8; nb++) {
        int c = h * HD_ + nb * 8 + 2 * tig;
        float2 o0 = make_float2(oacc[nb][0] * inv0, oacc[nb][1] * inv0);
        float2 o1 = make_float2(oacc[nb][2] * inv1, oacc[nb][3] * inv1);
        *(float2*)&O[((size_t)(b * S_ + r0g)) * (NH_*HD_) + c] = o0;
        *(float2*)&O[((size_t)(b * S_ + r1g)) * (NH_*HD_) + c] = o1;
    }
}

// ---------------------------------------------------------------------------
// Launch. Inputs: 0 query, 1 key, 2 value, 3 attn_mask, 4 Wq, 5 Wk, 6 Wv, 7 Wo
// ---------------------------------------------------------------------------
extern "C" void kernel_launch(void* const* d_in, const int* in_sizes, int n_in,
                              void* d_out, int out_size)
{
    const float* query = (const float*)d_in[0];
    const float* key   = (const float*)d_in[1];
    const float* value = (const float*)d_in[2];
    const float* Wq    = (const float*)d_in[4];
    const float* Wk    = (const float*)d_in[5];
    const float* Wv    = (const float*)d_in[6];
    const float* Wo    = (const float*)d_in[7];
    float* out = (float*)d_out;

    float *q, *k, *v, *attn;
    cudaGetSymbolAddress((void**)&q,    g_q);
    cudaGetSymbolAddress((void**)&k,    g_k);
    cudaGetSymbolAddress((void**)&v,    g_v);
    cudaGetSymbolAddress((void**)&attn, g_attn);

    dim3 thr(256);
    gemm_tf32_kernel<<<dim3((NH_*HD_)/BN, MTOT/BM), thr>>>(query, Wq, q, MTOT, NH_*HD_, E_);
    gemm_tf32_kernel<<<dim3((NKV_*HD_)/BN, MTOT/BM), thr>>>(key,   Wk, k, MTOT, NKV_*HD_, E_);
    gemm_tf32_kernel<<<dim3((NKV_*HD_)/BN, MTOT/BM), thr>>>(value, Wv, v, MTOT, NKV_*HD_, E_);

    attn_mma_kernel<<<dim3(S_/ABQ, NH_, B_), dim3(128)>>>(q, k, v, attn);

    gemm_tf32_kernel<<<dim3(E_/BN, MTOT/BM), thr>>>(attn, Wo, out, MTOT, E_, E_);
}

// round 6
// speedup vs baseline: 2.5516x; 1.2487x over previous
#include <cuda_runtime.h>
#include <cuda_bf16.h>
#include <mma.h>
#include <cstdint>

using namespace nvcuda;

// Problem constants
#define B_  2
#define S_  2048
#define E_  1024
#define NH_ 16
#define NKV_ 4
#define HD_ 64
#define GS_ 4
#define MTOT (B_*S_)    // 4096

// Scratch
__device__ float g_q[MTOT * (NH_*HD_)];
__device__ float g_k[MTOT * (NKV_*HD_)];
__device__ float g_v[MTOT * (NKV_*HD_)];
__device__ float g_attn[MTOT * (NH_*HD_)];

// ---------------------------------------------------------------------------
// tf32 GEMM with cp.async double buffering: C[M,N] = X[M,K] @ W[N,K]^T
// Block 128x128, BK=16 x 2 stages, 8 warps, warp tile 64x32 (4x2 wmma 16x16x8).
// ---------------------------------------------------------------------------
#define BM 128
#define BN 128
#define GBK 16
#define GPAD (GBK + 4)   // 20 floats = 80B rows (16B multiple)

__global__ __launch_bounds__(256)
void gemm_tf32_kernel(const float* __restrict__ X, const float* __restrict__ W,
                      float* __restrict__ C, int M, int N, int K)
{
    __shared__ float Xs[2][BM][GPAD];
    __shared__ float Ws[2][BN][GPAD];

    const int tid = threadIdx.x;
    const int wid = tid >> 5;
    const int wr  = wid & 1;
    const int wc  = wid >> 1;
    const int m0  = blockIdx.y * BM;
    const int n0  = blockIdx.x * BN;

    wmma::fragment<wmma::accumulator, 16, 16, 8, float> acc[4][2];
    #pragma unroll
    for (int i = 0; i < 4; i++)
        #pragma unroll
        for (int j = 0; j < 2; j++)
            wmma::fill_fragment(acc[i][j], 0.0f);

    auto prefetch = [&](int kt, int st) {
        const int k0 = kt * GBK;
        #pragma unroll
        for (int l = 0; l < 2; l++) {
            int idx = tid + l * 256;       // 0..511 float4 slots
            int r   = idx >> 2;            // 0..127
            int c4  = idx & 3;             // 0..3
            uint32_t dx = (uint32_t)__cvta_generic_to_shared(&Xs[st][r][c4 * 4]);
            uint32_t dw = (uint32_t)__cvta_generic_to_shared(&Ws[st][r][c4 * 4]);
            const float* sx = &X[(size_t)(m0 + r) * K + k0 + c4 * 4];
            const float* sw = &W[(size_t)(n0 + r) * K + k0 + c4 * 4];
            asm volatile("cp.async.cg.shared.global [%0], [%1], 16;" :: "r"(dx), "l"(sx));
            asm volatile("cp.async.cg.shared.global [%0], [%1], 16;" :: "r"(dw), "l"(sw));
        }
        asm volatile("cp.async.commit_group;");
    };

    const int nKT = K / GBK;
    prefetch(0, 0);

    for (int kt = 0; kt < nKT; kt++) {
        asm volatile("cp.async.wait_group 0;");
        __syncthreads();
        if (kt + 1 < nKT) prefetch(kt + 1, (kt + 1) & 1);
        const int st = kt & 1;

        #pragma unroll
        for (int ks = 0; ks < GBK; ks += 8) {
            wmma::fragment<wmma::matrix_a, 16, 16, 8, wmma::precision::tf32, wmma::row_major> a[4];
            wmma::fragment<wmma::matrix_b, 16, 16, 8, wmma::precision::tf32, wmma::col_major> bfr[2];
            #pragma unroll
            for (int i = 0; i < 4; i++) {
                wmma::load_matrix_sync(a[i], &Xs[st][wr * 64 + i * 16][ks], GPAD);
                #pragma unroll
                for (int t = 0; t < a[i].num_elements; t++)
                    a[i].x[t] = wmma::__float_to_tf32(a[i].x[t]);
            }
            #pragma unroll
            for (int j = 0; j < 2; j++) {
                wmma::load_matrix_sync(bfr[j], &Ws[st][wc * 32 + j * 16][ks], GPAD);
                #pragma unroll
                for (int t = 0; t < bfr[j].num_elements; t++)
                    bfr[j].x[t] = wmma::__float_to_tf32(bfr[j].x[t]);
            }
            #pragma unroll
            for (int i = 0; i < 4; i++)
                #pragma unroll
                for (int j = 0; j < 2; j++)
                    wmma::mma_sync(acc[i][j], a[i], bfr[j], acc[i][j]);
        }
    }

    #pragma unroll
    for (int i = 0; i < 4; i++)
        #pragma unroll
        for (int j = 0; j < 2; j++)
            wmma::store_matrix_sync(&C[(size_t)(m0 + wr * 64 + i * 16) * N + n0 + wc * 32 + j * 16],
                                    acc[i][j], N, wmma::mem_row_major);
}

// ---------------------------------------------------------------------------
// Flash attention with 2-way bf16 split (hi+lo), mma.m16n8k16.
// CTA 128 thr / 4 warps. BQ=64 (16 rows/warp), BK=32, HD=64.
// K packed bf16x2 along head-dim: sK[key][d/2]. V packed bf16x2 along keys:
// sV[dim][key/2]. Q/P split per-fragment. Error ~2^-16 per product.
// ---------------------------------------------------------------------------
#define ABQ 64
#define ABK 32

__device__ __forceinline__ uint32_t pack2(float x, float y) {
    __nv_bfloat162 t = __floats2bfloat162_rn(x, y);
    return *(uint32_t*)&t;
}
__device__ __forceinline__ float bf16hi(float x) {
    return __bfloat162float(__float2bfloat16_rn(x));
}
__device__ __forceinline__ void split2(float2 v, uint32_t& hi, uint32_t& lo) {
    float hx = bf16hi(v.x), hy = bf16hi(v.y);
    hi = pack2(hx, hy);
    lo = pack2(v.x - hx, v.y - hy);
}
__device__ __forceinline__ void mma_bf16(float c[4], const uint32_t a[4],
                                         uint32_t b0, uint32_t b1)
{
    asm volatile(
        "mma.sync.aligned.m16n8k16.row.col.f32.bf16.bf16.f32 "
        "{%0,%1,%2,%3}, {%4,%5,%6,%7}, {%8,%9}, {%0,%1,%2,%3};"
        : "+f"(c[0]), "+f"(c[1]), "+f"(c[2]), "+f"(c[3])
        : "r"(a[0]), "r"(a[1]), "r"(a[2]), "r"(a[3]), "r"(b0), "r"(b1));
}

__global__ __launch_bounds__(128, 4)
void attn_mma_kernel(const float* __restrict__ Q, const float* __restrict__ K,
                     const float* __restrict__ V, float* __restrict__ O)
{
    // K region: 2 * 32*36 u32 = 9216B ; V region: 2 * 64*20 u32 = 10240B
    // sQ ([64][68] float = 17408B) aliases the K+V region pre-loop.
    __shared__ __align__(16) unsigned char smem_raw[(2 * 32 * 36 + 2 * 64 * 20) * 4];
    __shared__ float sP[4][16 * 36];

    uint32_t (*sKhi)[36] = (uint32_t(*)[36])smem_raw;
    uint32_t (*sKlo)[36] = sKhi + 32;
    uint32_t (*sVhi)[20] = (uint32_t(*)[20])(smem_raw + 2 * 32 * 36 * 4);
    uint32_t (*sVlo)[20] = sVhi + 64;
    float* sQ = (float*)smem_raw;

    const int qb   = gridDim.x - 1 - blockIdx.x;
    const int h    = blockIdx.y;
    const int b    = blockIdx.z;
    const int kvh  = h >> 2;
    const int tid  = threadIdx.x;
    const int lane = tid & 31;
    const int w    = tid >> 5;
    const int g    = lane >> 2;
    const int tig  = lane & 3;

    const float scale = 0.125f;

    // ---- stage Q tile [64][64] scaled ----
    for (int i = tid; i < 64 * 16; i += 128) {
        int r = i >> 4, c4 = i & 15;
        float4 qv = *(const float4*)&Q[((size_t)(b * S_ + qb * ABQ + r)) * (NH_*HD_) + h * HD_ + c4 * 4];
        qv.x *= scale; qv.y *= scale; qv.z *= scale; qv.w *= scale;
        *(float4*)&sQ[r * 68 + c4 * 4] = qv;
    }
    __syncthreads();

    // ---- Q A-fragments (bf16 hi/lo), 4 K-chunks of 16 ----
    uint32_t qhi[4][4], qlo[4][4];
    {
        const int ra = w * 16 + g;
        #pragma unroll
        for (int kc = 0; kc < 4; kc++) {
            float2 x0 = *(float2*)&sQ[ra * 68 + kc * 16 + 2 * tig];
            float2 x1 = *(float2*)&sQ[(ra + 8) * 68 + kc * 16 + 2 * tig];
            float2 x2 = *(float2*)&sQ[ra * 68 + kc * 16 + 2 * tig + 8];
            float2 x3 = *(float2*)&sQ[(ra + 8) * 68 + kc * 16 + 2 * tig + 8];
            split2(x0, qhi[kc][0], qlo[kc][0]);
            split2(x1, qhi[kc][1], qlo[kc][1]);
            split2(x2, qhi[kc][2], qlo[kc][2]);
            split2(x3, qhi[kc][3], qlo[kc][3]);
        }
    }
    __syncthreads();

    float oacc[8][4];
    #pragma unroll
    for (int nb = 0; nb < 8; nb++)
        #pragma unroll
        for (int e = 0; e < 4; e++) oacc[nb][e] = 0.f;
    float m0 = -1e30f, m1 = -1e30f, l0 = 0.f, l1 = 0.f;

    const int r0g = qb * ABQ + w * 16 + g;
    const int r1g = r0g + 8;
    const int wRowMax = qb * ABQ + w * 16 + 15;
    const int nKT = 2 * qb + 2;

    for (int kt = 0; kt < nKT; kt++) {
        // ---- K tile: sK[key][d/2] bf16x2 packed along d ----
        for (int i = tid; i < 512; i += 128) {
            int r = i >> 4, c4 = i & 15;
            float4 kv = *(const float4*)&K[((size_t)(b * S_ + kt * ABK + r)) * (NKV_*HD_) + kvh * HD_ + c4 * 4];
            uint32_t h0, lo0, h1, lo1;
            split2(make_float2(kv.x, kv.y), h0, lo0);
            split2(make_float2(kv.z, kv.w), h1, lo1);
            sKhi[r][c4 * 2] = h0; sKhi[r][c4 * 2 + 1] = h1;
            sKlo[r][c4 * 2] = lo0; sKlo[r][c4 * 2 + 1] = lo1;
        }
        // ---- V tile: sV[dim][key/2] bf16x2 packed along keys ----
        for (int i = tid; i < 256; i += 128) {
            int kp = i & 15, c4 = i >> 4;
            size_t g0 = ((size_t)(b * S_ + kt * ABK + 2 * kp)) * (NKV_*HD_) + kvh * HD_ + c4 * 4;
            float4 va = *(const float4*)&V[g0];
            float4 vb = *(const float4*)&V[g0 + NKV_*HD_];
            float aa[4] = {va.x, va.y, va.z, va.w};
            float bb[4] = {vb.x, vb.y, vb.z, vb.w};
            #pragma unroll
            for (int dd = 0; dd < 4; dd++) {
                float ha = bf16hi(aa[dd]), hb = bf16hi(bb[dd]);
                sVhi[c4 * 4 + dd][kp] = pack2(ha, hb);
                sVlo[c4 * 4 + dd][kp] = pack2(aa[dd] - ha, bb[dd] - hb);
            }
        }
        __syncthreads();

        if (kt * ABK <= wRowMax) {
            // ---- S = Q @ K^T ----
            float sacc[4][4];
            #pragma unroll
            for (int nb = 0; nb < 4; nb++)
                #pragma unroll
                for (int e = 0; e < 4; e++) sacc[nb][e] = 0.f;

            #pragma unroll
            for (int kc = 0; kc < 4; kc++) {
                #pragma unroll
                for (int nb = 0; nb < 4; nb++) {
                    const int key = nb * 8 + g;
                    uint32_t bh0 = sKhi[key][kc * 8 + tig], bh1 = sKhi[key][kc * 8 + tig + 4];
                    uint32_t bl0 = sKlo[key][kc * 8 + tig], bl1 = sKlo[key][kc * 8 + tig + 4];
                    mma_bf16(sacc[nb], qhi[kc], bl0, bl1);
                    mma_bf16(sacc[nb], qlo[kc], bh0, bh1);
                    mma_bf16(sacc[nb], qhi[kc], bh0, bh1);
                }
            }

            // ---- causal mask + online softmax ----
            float mn0 = m0, mn1 = m1;
            #pragma unroll
            for (int nb = 0; nb < 4; nb++) {
                #pragma unroll
                for (int e = 0; e < 2; e++) {
                    int col = kt * ABK + nb * 8 + 2 * tig + e;
                    if (col > r0g) sacc[nb][e]     = -1e30f;
                    if (col > r1g) sacc[nb][e + 2] = -1e30f;
                    mn0 = fmaxf(mn0, sacc[nb][e]);
                    mn1 = fmaxf(mn1, sacc[nb][e + 2]);
                }
            }
            mn0 = fmaxf(mn0, __shfl_xor_sync(0xffffffffu, mn0, 1));
            mn0 = fmaxf(mn0, __shfl_xor_sync(0xffffffffu, mn0, 2));
            mn1 = fmaxf(mn1, __shfl_xor_sync(0xffffffffu, mn1, 1));
            mn1 = fmaxf(mn1, __shfl_xor_sync(0xffffffffu, mn1, 2));

            const float corr0 = __expf(m0 - mn0);
            const float corr1 = __expf(m1 - mn1);
            m0 = mn0; m1 = mn1;
            l0 *= corr0; l1 *= corr1;
            #pragma unroll
            for (int nb = 0; nb < 8; nb++) {
                oacc[nb][0] *= corr0; oacc[nb][1] *= corr0;
                oacc[nb][2] *= corr1; oacc[nb][3] *= corr1;
            }

            #pragma unroll
            for (int nb = 0; nb < 4; nb++) {
                float p0 = __expf(sacc[nb][0] - mn0);
                float p1 = __expf(sacc[nb][1] - mn0);
                float p2 = __expf(sacc[nb][2] - mn1);
                float p3 = __expf(sacc[nb][3] - mn1);
                l0 += p0 + p1; l1 += p2 + p3;
                int c = nb * 8 + 2 * tig;
                sP[w][g * 36 + c]           = p0;
                sP[w][g * 36 + c + 1]       = p1;
                sP[w][(g + 8) * 36 + c]     = p2;
                sP[w][(g + 8) * 36 + c + 1] = p3;
            }
            __syncwarp();

            // ---- O += P @ V ----
            #pragma unroll
            for (int kc = 0; kc < 2; kc++) {
                float2 x0 = *(float2*)&sP[w][g * 36 + kc * 16 + 2 * tig];
                float2 x1 = *(float2*)&sP[w][(g + 8) * 36 + kc * 16 + 2 * tig];
                float2 x2 = *(float2*)&sP[w][g * 36 + kc * 16 + 2 * tig + 8];
                float2 x3 = *(float2*)&sP[w][(g + 8) * 36 + kc * 16 + 2 * tig + 8];
                uint32_t phi[4], plo[4];
                split2(x0, phi[0], plo[0]);
                split2(x1, phi[1], plo[1]);
                split2(x2, phi[2], plo[2]);
                split2(x3, phi[3], plo[3]);
                #pragma unroll
                for (int nb = 0; nb < 8; nb++) {
                    const int d = nb * 8 + g;
                    uint32_t bh0 = sVhi[d][kc * 8 + tig], bh1 = sVhi[d][kc * 8 + tig + 4];
                    uint32_t bl0 = sVlo[d][kc * 8 + tig], bl1 = sVlo[d][kc * 8 + tig + 4];
                    mma_bf16(oacc[nb], phi, bl0, bl1);
                    mma_bf16(oacc[nb], plo, bh0, bh1);
                    mma_bf16(oacc[nb], phi, bh0, bh1);
                }
            }
        }
        __syncthreads();
    }

    // ---- epilogue ----
    l0 += __shfl_xor_sync(0xffffffffu, l0, 1);
    l0 += __shfl_xor_sync(0xffffffffu, l0, 2);
    l1 += __shfl_xor_sync(0xffffffffu, l1, 1);
    l1 += __shfl_xor_sync(0xffffffffu, l1, 2);
    const float inv0 = 1.f / l0;
    const float inv1 = 1.f / l1;

    #pragma unroll
    for (int nb = 0; nb < 8; nb++) {
        int c = h * HD_ + nb * 8 + 2 * tig;
        float2 o0 = make_float2(oacc[nb][0] * inv0, oacc[nb][1] * inv0);
        float2 o1 = make_float2(oacc[nb][2] * inv1, oacc[nb][3] * inv1);
        *(float2*)&O[((size_t)(b * S_ + r0g)) * (NH_*HD_) + c] = o0;
        *(float2*)&O[((size_t)(b * S_ + r1g)) * (NH_*HD_) + c] = o1;
    }
}

// ---------------------------------------------------------------------------
// Launch. Inputs: 0 query, 1 key, 2 value, 3 attn_mask, 4 Wq, 5 Wk, 6 Wv, 7 Wo
// ---------------------------------------------------------------------------
extern "C" void kernel_launch(void* const* d_in, const int* in_sizes, int n_in,
                              void* d_out, int out_size)
{
    const float* query = (const float*)d_in[0];
    const float* key   = (const float*)d_in[1];
    const float* value = (const float*)d_in[2];
    const float* Wq    = (const float*)d_in[4];
    const float* Wk    = (const float*)d_in[5];
    const float* Wv    = (const float*)d_in[6];
    const float* Wo    = (const float*)d_in[7];
    float* out = (float*)d_out;

    float *q, *k, *v, *attn;
    cudaGetSymbolAddress((void**)&q,    g_q);
    cudaGetSymbolAddress((void**)&k,    g_k);
    cudaGetSymbolAddress((void**)&v,    g_v);
    cudaGetSymbolAddress((void**)&attn, g_attn);

    dim3 thr(256);
    gemm_tf32_kernel<<<dim3((NH_*HD_)/BN, MTOT/BM), thr>>>(query, Wq, q, MTOT, NH_*HD_, E_);
    gemm_tf32_kernel<<<dim3((NKV_*HD_)/BN, MTOT/BM), thr>>>(key,   Wk, k, MTOT, NKV_*HD_, E_);
    gemm_tf32_kernel<<<dim3((NKV_*HD_)/BN, MTOT/BM), thr>>>(value, Wv, v, MTOT, NKV_*HD_, E_);

    attn_mma_kernel<<<dim3(S_/ABQ, NH_, B_), dim3(128)>>>(q, k, v, attn);

    gemm_tf32_kernel<<<dim3(E_/BN, MTOT/BM), thr>>>(attn, Wo, out, MTOT, E_, E_);
}